// round 1
// baseline (speedup 1.0000x reference)
#include <cuda_runtime.h>
#include <cstdint>
#include <cstddef>

#define N_NODES 100000
#define N_EDGES 300000
#define N_GRAPHS 2048

typedef unsigned long long ull;

// ---------------- scratch (no allocations allowed) ----------------
__device__ float g_h[(size_t)N_NODES * 512];
__device__ float g_z[(size_t)N_NODES * 512];
__device__ float g_t[(size_t)N_NODES * 512];
__device__ float g_pool[(size_t)N_GRAPHS * 512];

// ---------------- packed f32x2 helpers (FFMA2) ----------------
__device__ __forceinline__ ull pack2(float lo, float hi) {
    ull r;
    asm("mov.b64 %0, {%1, %2};" : "=l"(r) : "f"(lo), "f"(hi));
    return r;
}
__device__ __forceinline__ void unpack2(ull v, float& lo, float& hi) {
    asm("mov.b64 {%0, %1}, %2;" : "=f"(lo), "=f"(hi) : "l"(v));
}
__device__ __forceinline__ void fma2(ull& d, ull a, ull b) {
    asm("fma.rn.f32x2 %0, %1, %2, %3;" : "=l"(d) : "l"(a), "l"(b), "l"(d));
}

// ---------------- node feature embed: h = x @ W_embed + b ----------------
__global__ void embed_kernel(const float* __restrict__ x,
                             const float* __restrict__ W,
                             const float* __restrict__ b,
                             float* __restrict__ h) {
    int n = blockIdx.x;
    int t = threadIdx.x;  // 128
    __shared__ float xs[40];
    if (t < 40) xs[t] = x[n * 40 + t];
    __syncthreads();
    float acc = b[t];
#pragma unroll
    for (int k = 0; k < 40; k++) acc = fmaf(xs[k], W[k * 128 + t], acc);
    h[(size_t)n * 128 + t] = acc;
}

// ---------------- z = (1+eps)*h ----------------
__global__ void scale_kernel(const float4* __restrict__ h, float4* __restrict__ z,
                             const float* __restrict__ eps, int l, int n4) {
    int i = blockIdx.x * blockDim.x + threadIdx.x;
    if (i >= n4) return;
    float s = 1.0f + eps[l];
    float4 v = h[i];
    v.x *= s; v.y *= s; v.z *= s; v.w *= s;
    z[i] = v;
}

// ---------------- z[dst] += h[src] over edges (vectorized atomics) --------
__global__ void scatter_kernel(const int* __restrict__ ei,
                               const float* __restrict__ h,
                               float* __restrict__ z,
                               int shift, int mask, int ntot) {
    int i = blockIdx.x * blockDim.x + threadIdx.x;
    if (i >= ntot) return;
    int e = i >> shift;
    int c = i & mask;
    int s = ei[e];
    int d = ei[N_EDGES + e];
    int D = (mask + 1) << 2;
    float4 v = *(const float4*)(h + (size_t)s * D + (size_t)c * 4);
    float* zp = z + (size_t)d * D + (size_t)c * 4;
    atomicAdd(zp + 0, v.x);
    atomicAdd(zp + 1, v.y);
    atomicAdd(zp + 2, v.z);
    atomicAdd(zp + 3, v.w);
}

// ---------------- SGEMM: C = act(A[M,K] @ B[K,N] + bias) ----------------
// 128x128 tile, BK=8, 256 threads, 8x8 per thread, f32x2 packed FMA.
__global__ __launch_bounds__(256)
void gemm_kernel(const float* __restrict__ A, const float* __restrict__ B,
                 const float* __restrict__ bias, float* __restrict__ C,
                 int M, int K, int N, int relu) {
    __shared__ __align__(16) float As[8][128];
    __shared__ __align__(16) float Bs[8][128];

    const int tid = threadIdx.x;
    const int bm = blockIdx.y * 128;
    const int bn = blockIdx.x * 128;
    const int tr = tid >> 4;    // 0..15
    const int tc = tid & 15;    // 0..15

    // global->smem load mapping (one float4 of A and one of B per thread)
    const int arow = tid >> 1;          // 0..127
    const int acol = (tid & 1) << 2;    // 0 or 4
    const int brow = tid >> 5;          // 0..7
    const int bcol = (tid & 31) << 2;   // 0..124

    const int grow = bm + arow;
    const bool a_ok = grow < M;
    const float* Ap = A + (size_t)grow * K + acol;
    const float* Bp = B + (size_t)brow * N + bn + bcol;

    ull acc[8][4] = {};   // 8 rows x 4 col-pairs (8 cols)

    for (int k0 = 0; k0 < K; k0 += 8) {
        float4 av = a_ok ? *(const float4*)(Ap + k0) : make_float4(0.f, 0.f, 0.f, 0.f);
        float4 bv = *(const float4*)(Bp + (size_t)k0 * N);
        As[acol + 0][arow] = av.x;
        As[acol + 1][arow] = av.y;
        As[acol + 2][arow] = av.z;
        As[acol + 3][arow] = av.w;
        *(float4*)&Bs[brow][bcol] = bv;
        __syncthreads();
#pragma unroll
        for (int kk = 0; kk < 8; kk++) {
            const float4 a0 = *(const float4*)&As[kk][tr * 4];
            const float4 a1 = *(const float4*)&As[kk][64 + tr * 4];
            const float4 b0 = *(const float4*)&Bs[kk][tc * 4];
            const float4 b1 = *(const float4*)&Bs[kk][64 + tc * 4];
            float a[8] = {a0.x, a0.y, a0.z, a0.w, a1.x, a1.y, a1.z, a1.w};
            ull bp[4];
            bp[0] = pack2(b0.x, b0.y);
            bp[1] = pack2(b0.z, b0.w);
            bp[2] = pack2(b1.x, b1.y);
            bp[3] = pack2(b1.z, b1.w);
#pragma unroll
            for (int i = 0; i < 8; i++) {
                ull ap = pack2(a[i], a[i]);
                fma2(acc[i][0], ap, bp[0]);
                fma2(acc[i][1], ap, bp[1]);
                fma2(acc[i][2], ap, bp[2]);
                fma2(acc[i][3], ap, bp[3]);
            }
        }
        __syncthreads();
    }

    // epilogue: bias + optional relu
    float bias0[4], bias1[4];
#pragma unroll
    for (int j = 0; j < 4; j++) {
        bias0[j] = bias[bn + tc * 4 + j];
        bias1[j] = bias[bn + 64 + tc * 4 + j];
    }
#pragma unroll
    for (int i = 0; i < 8; i++) {
        int row = bm + ((i < 4) ? (tr * 4 + i) : (64 + tr * 4 + (i - 4)));
        if (row >= M) continue;
        float o[8];
        unpack2(acc[i][0], o[0], o[1]);
        unpack2(acc[i][1], o[2], o[3]);
        unpack2(acc[i][2], o[4], o[5]);
        unpack2(acc[i][3], o[6], o[7]);
#pragma unroll
        for (int j = 0; j < 4; j++) {
            o[j] += bias0[j];
            o[4 + j] += bias1[j];
        }
        if (relu) {
#pragma unroll
            for (int j = 0; j < 8; j++) o[j] = fmaxf(o[j], 0.f);
        }
        *(float4*)(C + (size_t)row * N + bn + tc * 4) =
            make_float4(o[0], o[1], o[2], o[3]);
        *(float4*)(C + (size_t)row * N + bn + 64 + tc * 4) =
            make_float4(o[4], o[5], o[6], o[7]);
    }
}

// ---------------- pooled[batch[n]] += h[n]  (D = 512) ----------------
__global__ void pool_kernel(const int* __restrict__ batch,
                            const float* __restrict__ h,
                            float* __restrict__ pool, int ntot) {
    int i = blockIdx.x * blockDim.x + threadIdx.x;
    if (i >= ntot) return;
    int n = i >> 7;        // 128 float4 chunks per node
    int c = i & 127;
    int g = batch[n];
    float4 v = *(const float4*)(h + (size_t)n * 512 + (size_t)c * 4);
    float* p = pool + (size_t)g * 512 + (size_t)c * 4;
    atomicAdd(p + 0, v.x);
    atomicAdd(p + 1, v.y);
    atomicAdd(p + 2, v.z);
    atomicAdd(p + 3, v.w);
}

// ---------------- out[g] = pooled[g] . W_task + b ----------------
__global__ void task_kernel(const float* __restrict__ pool,
                            const float* __restrict__ W,
                            const float* __restrict__ b,
                            float* __restrict__ out) {
    int g = blockIdx.x;
    int t = threadIdx.x;  // 128
    const float* p = pool + (size_t)g * 512;
    float acc = 0.f;
#pragma unroll
    for (int k = t; k < 512; k += 128) acc = fmaf(p[k], W[k], acc);
#pragma unroll
    for (int o = 16; o > 0; o >>= 1) acc += __shfl_xor_sync(0xffffffffu, acc, o);
    __shared__ float s[4];
    if ((t & 31) == 0) s[t >> 5] = acc;
    __syncthreads();
    if (t == 0) out[g] = s[0] + s[1] + s[2] + s[3] + b[0];
}

// ---------------- launch ----------------
extern "C" void kernel_launch(void* const* d_in, const int* in_sizes, int n_in,
                              void* d_out, int out_size) {
    const float* x       = (const float*)d_in[0];
    const int*   ei      = (const int*)d_in[1];     // edge_index [2, N_EDGES]
    const int*   batch   = (const int*)d_in[2];
    const float* W_embed = (const float*)d_in[3];
    const float* b_embed = (const float*)d_in[4];
    const float* eps     = (const float*)d_in[5];
    const float* W1[3] = {(const float*)d_in[6],  (const float*)d_in[10], (const float*)d_in[14]};
    const float* b1[3] = {(const float*)d_in[7],  (const float*)d_in[11], (const float*)d_in[15]};
    const float* W2[3] = {(const float*)d_in[8],  (const float*)d_in[12], (const float*)d_in[16]};
    const float* b2[3] = {(const float*)d_in[9],  (const float*)d_in[13], (const float*)d_in[17]};
    const float* W_task = (const float*)d_in[18];
    const float* b_task = (const float*)d_in[19];
    float* out = (float*)d_out;

    float *h, *z, *t, *pool;
    cudaGetSymbolAddress((void**)&h, g_h);
    cudaGetSymbolAddress((void**)&z, g_z);
    cudaGetSymbolAddress((void**)&t, g_t);
    cudaGetSymbolAddress((void**)&pool, g_pool);

    embed_kernel<<<N_NODES, 128>>>(x, W_embed, b_embed, h);

    const int Din[3]  = {128, 256, 256};
    const int Dmid[3] = {256, 256, 512};
    const int Dout[3] = {256, 256, 512};

    for (int l = 0; l < 3; l++) {
        int D = Din[l];
        int n4 = N_NODES * D / 4;
        scale_kernel<<<(n4 + 255) / 256, 256>>>((const float4*)h, (float4*)z, eps, l, n4);

        int shift = (D == 128) ? 5 : 6;
        int mask = (1 << shift) - 1;
        int ntot = N_EDGES << shift;
        scatter_kernel<<<(ntot + 255) / 256, 256>>>(ei, h, z, shift, mask, ntot);

        dim3 g1(Dmid[l] / 128, (N_NODES + 127) / 128);
        gemm_kernel<<<g1, 256>>>(z, W1[l], b1[l], t, N_NODES, D, Dmid[l], 1);

        dim3 g2(Dout[l] / 128, (N_NODES + 127) / 128);
        gemm_kernel<<<g2, 256>>>(t, W2[l], b2[l], h, N_NODES, Dmid[l], Dout[l],
                                 (l < 2) ? 1 : 0);
    }

    cudaMemsetAsync(pool, 0, (size_t)N_GRAPHS * 512 * sizeof(float));
    int ntot = N_NODES * 128;
    pool_kernel<<<(ntot + 255) / 256, 256>>>(batch, h, pool, ntot);
    task_kernel<<<N_GRAPHS, 128>>>(pool, W_task, b_task, out);
}

// round 4
// speedup vs baseline: 2.0457x; 2.0457x over previous
#include <cuda_runtime.h>
#include <cuda_bf16.h>
#include <cstdint>
#include <cstddef>

#define N_NODES 100000
#define N_EDGES 300000
#define N_GRAPHS 2048

// ---------------- scratch (no allocations allowed) ----------------
__device__ __align__(256) float g_h[(size_t)N_NODES * 512];
__device__ __align__(256) float g_z[(size_t)N_NODES * 512];
__device__ __align__(256) float g_t[(size_t)N_NODES * 512];
__device__ __align__(256) float g_pool[(size_t)N_GRAPHS * 512];
// converted weights: [N][K] bf16, hi and lo parts, 6 matrices packed
__device__ __align__(256) __nv_bfloat16 g_whi[622592];
__device__ __align__(256) __nv_bfloat16 g_wlo[622592];

// ---------------- helpers ----------------
__device__ __forceinline__ uint32_t smem_u32(const void* p) {
    uint32_t a;
    asm("{ .reg .u64 t; cvta.to.shared.u64 t, %1; cvt.u32.u64 %0, t; }"
        : "=r"(a) : "l"(p));
    return a;
}

#define LDM4(r, addr)                                                         \
    asm volatile("ldmatrix.sync.aligned.m8n8.x4.shared.b16 {%0,%1,%2,%3}, [%4];" \
                 : "=r"((r)[0]), "=r"((r)[1]), "=r"((r)[2]), "=r"((r)[3])     \
                 : "r"(addr))

#define MMA16816(c, a, b0, b1)                                                \
    asm volatile("mma.sync.aligned.m16n8k16.row.col.f32.bf16.bf16.f32 "        \
                 "{%0,%1,%2,%3}, {%4,%5,%6,%7}, {%8,%9}, {%0,%1,%2,%3};"       \
                 : "+f"((c)[0]), "+f"((c)[1]), "+f"((c)[2]), "+f"((c)[3])      \
                 : "r"((a)[0]), "r"((a)[1]), "r"((a)[2]), "r"((a)[3]),         \
                   "r"(b0), "r"(b1))

#define CP16(saddr, gaddr)                                                    \
    asm volatile("cp.async.cg.shared.global [%0], [%1], 16;" ::               \
                 "r"(saddr), "l"(gaddr))

// ---------------- weight prep: fp32 [K][N] -> bf16 hi/lo [N][K] ----------------
__global__ void prep_w(const float* __restrict__ W, __nv_bfloat16* __restrict__ hi,
                       __nv_bfloat16* __restrict__ lo, int K, int N) {
    int i = blockIdx.x * blockDim.x + threadIdx.x;
    if (i >= K * N) return;
    int k = i / N, n = i % N;
    float x = W[i];
    __nv_bfloat16 h = __float2bfloat16(x);
    float r = x - __bfloat162float(h);
    hi[(size_t)n * K + k] = h;
    lo[(size_t)n * K + k] = __float2bfloat16(r);
}

// ---------------- node feature embed: h = x @ W_embed + b ----------------
__global__ __launch_bounds__(256)
void embed_kernel(const float* __restrict__ x, const float* __restrict__ W,
                  const float* __restrict__ b, float* __restrict__ h) {
    __shared__ float Ws[40 * 128];
    __shared__ float xs[32 * 40];
    __shared__ float bs[128];
    int tid = threadIdx.x;
    int n0 = blockIdx.x * 32;
    for (int i = tid; i < 40 * 128; i += 256) Ws[i] = W[i];
    if (tid < 128) bs[tid] = b[tid];
    for (int i = tid; i < 32 * 40; i += 256) {
        int n = n0 + (i / 40);
        xs[i] = (n < N_NODES) ? x[(size_t)n * 40 + (i % 40)] : 0.f;
    }
    __syncthreads();
    for (int i = tid; i < 32 * 128; i += 256) {
        int nl = i >> 7, col = i & 127;
        int n = n0 + nl;
        if (n >= N_NODES) continue;
        float acc = bs[col];
#pragma unroll
        for (int k = 0; k < 40; k++) acc = fmaf(xs[nl * 40 + k], Ws[k * 128 + col], acc);
        h[(size_t)n * 128 + col] = acc;
    }
}

// ---------------- z = (1+eps)*h ----------------
__global__ void scale_kernel(const float4* __restrict__ h, float4* __restrict__ z,
                             const float* __restrict__ eps, int l, int n4) {
    int i = blockIdx.x * blockDim.x + threadIdx.x;
    if (i >= n4) return;
    float s = 1.0f + eps[l];
    float4 v = h[i];
    v.x *= s; v.y *= s; v.z *= s; v.w *= s;
    z[i] = v;
}

// ---------------- z[dst] += h[src] over edges (float4 REDG) --------
__global__ void scatter_kernel(const int* __restrict__ ei,
                               const float* __restrict__ h,
                               float* __restrict__ z,
                               int shift, int mask, int ntot) {
    int i = blockIdx.x * blockDim.x + threadIdx.x;
    if (i >= ntot) return;
    int e = i >> shift;
    int c = i & mask;
    int s = ei[e];
    int d = ei[N_EDGES + e];
    int D = (mask + 1) << 2;
    float4 v = *(const float4*)(h + (size_t)s * D + (size_t)c * 4);
    atomicAdd((float4*)(z + (size_t)d * D + (size_t)c * 4), v);
}

// ---------------- HMMA bf16x3 GEMM: C = act(A[M,K]@W[K,N]+bias) ----------------
// A fp32 row-major, converted in-kernel to bf16 hi/lo.
// W pre-converted to bf16 hi/lo in [N][K] layout.
// BM=128, BN=256, BK=32, 512 threads, 4x4 warps, warp tile 32x64.
// smem rows padded to 40 bf16 (80B) -> conflict-free ldmatrix.
#define STG_A_HI 0
#define STG_A_LO 10240
#define STG_B_HI 20480
#define STG_B_LO 40960
#define STG_SIZE 61440
#define GEMM_SMEM (2 * STG_SIZE)

__global__ __launch_bounds__(512, 1)
void mma_gemm(const float* __restrict__ A, const __nv_bfloat16* __restrict__ Bhi,
              const __nv_bfloat16* __restrict__ Blo, const float* __restrict__ bias,
              float* __restrict__ C, int M, int K, int N, int relu) {
    extern __shared__ char smem[];
    const int tid = threadIdx.x;
    const int lane = tid & 31;
    const int w = tid >> 5;
    const int wm = w & 3, wn = w >> 2;
    const int bm = blockIdx.y * 128;
    const int bn = blockIdx.x * 256;
    const uint32_t sbase = smem_u32(smem);

    // A loader mapping: thread -> (row, 8-float group)
    const int arow = tid >> 2;
    const int ag = tid & 3;
    const int agrow = bm + arow;
    const float4* Ap = (agrow < M)
        ? (const float4*)(A + (size_t)agrow * K + ag * 8) : nullptr;
    const uint32_t a_soff = (uint32_t)(arow * 80 + ag * 16);

    float acc[2][8][4];
#pragma unroll
    for (int i = 0; i < 2; i++)
#pragma unroll
        for (int j = 0; j < 8; j++)
#pragma unroll
            for (int q = 0; q < 4; q++) acc[i][j][q] = 0.f;

    const int S = K >> 5;
    float4 ar[2] = {make_float4(0,0,0,0), make_float4(0,0,0,0)};

    // ---- helpers as macros over locals ----
#define CP_B(st, k0)                                                          \
    {                                                                         \
        uint32_t sb_ = sbase + (st) * STG_SIZE;                               \
        _Pragma("unroll")                                                     \
        for (int j_ = 0; j_ < 2; j_++) {                                      \
            int idx_ = tid + j_ * 512;                                        \
            int n_ = idx_ >> 2, g_ = idx_ & 3;                                \
            size_t go_ = (size_t)(bn + n_) * K + (k0) + g_ * 8;               \
            uint32_t so_ = (uint32_t)(n_ * 80 + g_ * 16);                     \
            CP16(sb_ + STG_B_HI + so_, Bhi + go_);                            \
            CP16(sb_ + STG_B_LO + so_, Blo + go_);                            \
        }                                                                     \
        asm volatile("cp.async.commit_group;" ::: "memory");                  \
    }

#define LD_A(k0)                                                              \
    if (Ap) {                                                                 \
        ar[0] = Ap[(k0) >> 2];                                                \
        ar[1] = Ap[((k0) >> 2) + 1];                                          \
    }

#define ST_A(st)                                                              \
    {                                                                         \
        float v_[8] = {ar[0].x, ar[0].y, ar[0].z, ar[0].w,                    \
                       ar[1].x, ar[1].y, ar[1].z, ar[1].w};                   \
        uint32_t hw_[4], lw_[4];                                              \
        _Pragma("unroll")                                                     \
        for (int j_ = 0; j_ < 4; j_++) {                                      \
            __nv_bfloat162 hp_ = __floats2bfloat162_rn(v_[2*j_], v_[2*j_+1]); \
            float2 hf_ = __bfloat1622float2(hp_);                             \
            __nv_bfloat162 lp_ = __floats2bfloat162_rn(v_[2*j_] - hf_.x,      \
                                                       v_[2*j_+1] - hf_.y);   \
            hw_[j_] = *reinterpret_cast<uint32_t*>(&hp_);                     \
            lw_[j_] = *reinterpret_cast<uint32_t*>(&lp_);                     \
        }                                                                     \
        *(uint4*)(smem + (st) * STG_SIZE + STG_A_HI + a_soff) =               \
            make_uint4(hw_[0], hw_[1], hw_[2], hw_[3]);                       \
        *(uint4*)(smem + (st) * STG_SIZE + STG_A_LO + a_soff) =               \
            make_uint4(lw_[0], lw_[1], lw_[2], lw_[3]);                       \
    }

    // ---- prologue ----
    CP_B(0, 0);
    LD_A(0);
    ST_A(0);
    asm volatile("cp.async.wait_group 0;" ::: "memory");
    __syncthreads();

    // ldmatrix lane address components (byte offsets inside a stage)
    const uint32_t a_ld_row = (uint32_t)((wm * 32 + (lane & 15)) * 80);
    const uint32_t a_ld_col = (uint32_t)(((lane >> 4) & 1) * 16);
    const uint32_t b_ld_n = (uint32_t)((wn * 64 + ((lane >> 4) & 1) * 8 + (lane & 7)) * 80);
    const uint32_t b_ld_k = (uint32_t)(((lane >> 3) & 1) * 16);  // bytes (8 bf16)

    for (int s = 0; s < S; s++) {
        const int cst = s & 1;
        const int nst = cst ^ 1;
        if (s + 1 < S) {
            CP_B(nst, (s + 1) << 5);
            LD_A((s + 1) << 5);
        }
        // ---- compute stage cst ----
        const uint32_t sg = sbase + cst * STG_SIZE;
#pragma unroll
        for (int kh = 0; kh < 2; kh++) {
            uint32_t ahi[2][4], alo[2][4];
#pragma unroll
            for (int mt = 0; mt < 2; mt++) {
                uint32_t ad = sg + a_ld_row + (uint32_t)(mt * 16 * 80) +
                              (uint32_t)(kh * 32) + a_ld_col;
                LDM4(ahi[mt], ad + STG_A_HI);
                LDM4(alo[mt], ad + STG_A_LO);
            }
#pragma unroll
            for (int np = 0; np < 4; np++) {
                uint32_t bd = sg + b_ld_n + (uint32_t)(np * 16 * 80) +
                              (uint32_t)(kh * 32) + b_ld_k;
                uint32_t bh[4], bl[4];
                LDM4(bh, bd + STG_B_HI);
                LDM4(bl, bd + STG_B_LO);
#pragma unroll
                for (int mt = 0; mt < 2; mt++) {
                    MMA16816(acc[mt][np * 2], ahi[mt], bh[0], bh[1]);
                    MMA16816(acc[mt][np * 2], ahi[mt], bl[0], bl[1]);
                    MMA16816(acc[mt][np * 2], alo[mt], bh[0], bh[1]);
                    MMA16816(acc[mt][np * 2 + 1], ahi[mt], bh[2], bh[3]);
                    MMA16816(acc[mt][np * 2 + 1], ahi[mt], bl[2], bl[3]);
                    MMA16816(acc[mt][np * 2 + 1], alo[mt], bh[2], bh[3]);
                }
            }
        }
        if (s + 1 < S) {
            asm volatile("cp.async.wait_group 0;" ::: "memory");
            ST_A(nst);
            __syncthreads();
        }
    }

    // ---- epilogue: bias + relu, direct stores ----
#pragma unroll
    for (int mt = 0; mt < 2; mt++) {
        int r0 = bm + wm * 32 + mt * 16 + (lane >> 2);
#pragma unroll
        for (int nt = 0; nt < 8; nt++) {
            int col = bn + wn * 64 + nt * 8 + (lane & 3) * 2;
            float b0 = bias[col], b1 = bias[col + 1];
            float v0 = acc[mt][nt][0] + b0, v1 = acc[mt][nt][1] + b1;
            float v2 = acc[mt][nt][2] + b0, v3 = acc[mt][nt][3] + b1;
            if (relu) {
                v0 = fmaxf(v0, 0.f); v1 = fmaxf(v1, 0.f);
                v2 = fmaxf(v2, 0.f); v3 = fmaxf(v3, 0.f);
            }
            if (r0 < M) *(float2*)(C + (size_t)r0 * N + col) = make_float2(v0, v1);
            if (r0 + 8 < M) *(float2*)(C + (size_t)(r0 + 8) * N + col) = make_float2(v2, v3);
        }
    }
#undef CP_B
#undef LD_A
#undef ST_A
}

// ---------------- pooled[batch[n]] += h[n]  (D = 512) ----------------
__global__ void pool_kernel(const int* __restrict__ batch,
                            const float* __restrict__ h,
                            float* __restrict__ pool, int ntot) {
    int i = blockIdx.x * blockDim.x + threadIdx.x;
    if (i >= ntot) return;
    int n = i >> 7;
    int c = i & 127;
    int g = batch[n];
    float4 v = *(const float4*)(h + (size_t)n * 512 + (size_t)c * 4);
    atomicAdd((float4*)(pool + (size_t)g * 512 + (size_t)c * 4), v);
}

// ---------------- out[g] = pooled[g] . W_task + b ----------------
__global__ void task_kernel(const float* __restrict__ pool,
                            const float* __restrict__ W,
                            const float* __restrict__ b,
                            float* __restrict__ out) {
    int g = blockIdx.x;
    int t = threadIdx.x;  // 128
    const float* p = pool + (size_t)g * 512;
    float acc = 0.f;
#pragma unroll
    for (int k = t; k < 512; k += 128) acc = fmaf(p[k], W[k], acc);
#pragma unroll
    for (int o = 16; o > 0; o >>= 1) acc += __shfl_xor_sync(0xffffffffu, acc, o);
    __shared__ float s[4];
    if ((t & 31) == 0) s[t >> 5] = acc;
    __syncthreads();
    if (t == 0) out[g] = s[0] + s[1] + s[2] + s[3] + b[0];
}

// ---------------- launch ----------------
extern "C" void kernel_launch(void* const* d_in, const int* in_sizes, int n_in,
                              void* d_out, int out_size) {
    const float* x       = (const float*)d_in[0];
    const int*   ei      = (const int*)d_in[1];
    const int*   batch   = (const int*)d_in[2];
    const float* W_embed = (const float*)d_in[3];
    const float* b_embed = (const float*)d_in[4];
    const float* eps     = (const float*)d_in[5];
    const float* W1[3] = {(const float*)d_in[6],  (const float*)d_in[10], (const float*)d_in[14]};
    const float* b1[3] = {(const float*)d_in[7],  (const float*)d_in[11], (const float*)d_in[15]};
    const float* W2[3] = {(const float*)d_in[8],  (const float*)d_in[12], (const float*)d_in[16]};
    const float* b2[3] = {(const float*)d_in[9],  (const float*)d_in[13], (const float*)d_in[17]};
    const float* W_task = (const float*)d_in[18];
    const float* b_task = (const float*)d_in[19];
    float* out = (float*)d_out;

    float *h, *z, *t, *pool;
    __nv_bfloat16 *whi, *wlo;
    cudaGetSymbolAddress((void**)&h, g_h);
    cudaGetSymbolAddress((void**)&z, g_z);
    cudaGetSymbolAddress((void**)&t, g_t);
    cudaGetSymbolAddress((void**)&pool, g_pool);
    cudaGetSymbolAddress((void**)&whi, g_whi);
    cudaGetSymbolAddress((void**)&wlo, g_wlo);

    cudaFuncSetAttribute(mma_gemm, cudaFuncAttributeMaxDynamicSharedMemorySize, GEMM_SMEM);

    // weight offsets in [N][K] packed layout
    const size_t woff[6] = {0, 32768, 98304, 163840, 229376, 360448};
    const float* Wsrc[6] = {W1[0], W2[0], W1[1], W2[1], W1[2], W2[2]};
    const int Wk[6] = {128, 256, 256, 256, 256, 512};
    const int Wn[6] = {256, 256, 256, 256, 512, 512};
    for (int i = 0; i < 6; i++) {
        int tot = Wk[i] * Wn[i];
        prep_w<<<(tot + 255) / 256, 256>>>(Wsrc[i], whi + woff[i], wlo + woff[i],
                                           Wk[i], Wn[i]);
    }

    embed_kernel<<<(N_NODES + 31) / 32, 256>>>(x, W_embed, b_embed, h);

    const int Din[3]  = {128, 256, 256};
    const int Dmid[3] = {256, 256, 512};
    const int Dout[3] = {256, 256, 512};
    const int MT = (N_NODES + 127) / 128;   // 782

    for (int l = 0; l < 3; l++) {
        int D = Din[l];
        int n4 = N_NODES * D / 4;
        scale_kernel<<<(n4 + 255) / 256, 256>>>((const float4*)h, (float4*)z, eps, l, n4);

        int shift = (D == 128) ? 5 : 6;
        int mask = (1 << shift) - 1;
        int ntot = N_EDGES << shift;
        scatter_kernel<<<(ntot + 255) / 256, 256>>>(ei, h, z, shift, mask, ntot);

        mma_gemm<<<dim3(Dmid[l] / 256, MT), 512, GEMM_SMEM>>>(
            z, whi + woff[2 * l], wlo + woff[2 * l], b1[l], t,
            N_NODES, D, Dmid[l], 1);

        mma_gemm<<<dim3(Dout[l] / 256, MT), 512, GEMM_SMEM>>>(
            t, whi + woff[2 * l + 1], wlo + woff[2 * l + 1], b2[l], h,
            N_NODES, Dmid[l], Dout[l], (l < 2) ? 1 : 0);
    }

    cudaMemsetAsync(pool, 0, (size_t)N_GRAPHS * 512 * sizeof(float));
    int ntot = N_NODES * 128;
    pool_kernel<<<(ntot + 255) / 256, 256>>>(batch, h, pool, ntot);
    task_kernel<<<N_GRAPHS, 128>>>(pool, W_task, b_task, out);
}